// round 3
// baseline (speedup 1.0000x reference)
#include <cuda_runtime.h>
#include <cstdint>

// 2-layer LSTM, H=6, F=6, B=4096, T=1024.
// 4 batch elements per warp; within each 8-lane segment, lane k (k<6) owns
// hidden index k and computes ALL FOUR gate rows (i,f,g,o) for that k.
// Software-pipelined: iteration t computes layer0(t+1) and layer1(t) as two
// independent dependency chains -> ~half the serial critical path per step.
// Weights pre-scaled by -log2(e) / -2log2(e) so activations are ex2+rcp only.

#define WARPS_PER_BLOCK 4
#define THREADS (WARPS_PER_BLOCK * 32)
#define ELEMS_PER_WARP 4
#define T_LEN 1024
#define TCHUNK 32
#define NCHUNK (T_LEN / TCHUNK)       // 32
#define CSTRIDE 200                   // padded per-element stride (floats)
#define CSTRIDE4 (CSTRIDE / 4)

#define L2E 1.4426950408889634f
#define NS2 (-2.0f * L2E)

__device__ __forceinline__ float ex2f(float x) {
    float y; asm("ex2.approx.f32 %0, %1;" : "=f"(y) : "f"(x)); return y;
}
__device__ __forceinline__ float rcpf(float x) {
    float y; asm("rcp.approx.f32 %0, %1;" : "=f"(y) : "f"(x)); return y;
}
__device__ __forceinline__ float sigp(float zs) {          // z pre-scaled by -log2(e)
    return rcpf(1.0f + ex2f(zs));
}
__device__ __forceinline__ float tanhp(float zs) {         // z pre-scaled by -2log2(e)
    return fmaf(2.0f, rcpf(1.0f + ex2f(zs)), -1.0f);
}

__global__ __launch_bounds__(THREADS, 1)
void lstm2_kernel(const float* __restrict__ x,
                  const float* __restrict__ wih0, const float* __restrict__ whh0,
                  const float* __restrict__ bih0, const float* __restrict__ bhh0,
                  const float* __restrict__ wih1, const float* __restrict__ whh1,
                  const float* __restrict__ bih1, const float* __restrict__ bhh1,
                  float* __restrict__ out)
{
    __shared__ float sx[2][WARPS_PER_BLOCK][ELEMS_PER_WARP * CSTRIDE];
    __shared__ float so[WARPS_PER_BLOCK][ELEMS_PER_WARP * CSTRIDE];

    const int lane = threadIdx.x & 31;
    const int warp = threadIdx.x >> 5;
    const int e    = lane >> 3;         // element within warp
    const int s    = lane & 7;          // sub-lane within segment
    const int k    = (s < 6) ? s : 0;   // hidden index owned

    const int b0 = (blockIdx.x * WARPS_PER_BLOCK + warp) * ELEMS_PER_WARP;

    // per-lane weight rows (i,f,g,o of hidden index k), pre-scaled
    float wiA[4][6], whA[4][6], wiB[4][6], whB[4][6], bA[4], bB[4];
#pragma unroll
    for (int g = 0; g < 4; g++) {
        const float sc = (g == 2) ? NS2 : (-L2E);
        const int row = g * 6 + k;
#pragma unroll
        for (int q = 0; q < 6; q++) {
            wiA[g][q] = wih0[row * 6 + q] * sc;
            whA[g][q] = whh0[row * 6 + q] * sc;
            wiB[g][q] = wih1[row * 6 + q] * sc;
            whB[g][q] = whh1[row * 6 + q] * sc;
        }
        bA[g] = (bih0[row] + bhh0[row]) * sc;
        bB[g] = (bih1[row] + bhh1[row]) * sc;
    }

    float hb0[6], hb1[6];
#pragma unroll
    for (int q = 0; q < 6; q++) { hb0[q] = 0.0f; hb1[q] = 0.0f; }
    float c0 = 0.0f, c1 = 0.0f;

    // ---- chunk staging helper (32 timesteps x 6 floats x 4 elements) ----
    auto stage = [&](int c, int buf) {
        float4* dst = reinterpret_cast<float4*>(sx[buf][warp]);
#pragma unroll
        for (int i = 0; i < 6; i++) {
            int idx = i * 32 + lane;                 // 0..191
            int ee  = idx / 48;
            int off = idx - ee * 48;
            const float4* src = reinterpret_cast<const float4*>(
                x + (size_t)(b0 + ee) * (T_LEN * 6) + c * (TCHUNK * 6));
            dst[ee * CSTRIDE4 + off] = src[off];
        }
    };

    // ---- prologue: stage chunk 0, compute layer0 for t=0 ----
    stage(0, 0);
    __syncwarp();
    {
        const float* xr = &sx[0][warp][e * CSTRIDE];
        float zi = bA[0], zf = bA[1], zg = bA[2], zo = bA[3];
#pragma unroll
        for (int q = 0; q < 6; q++) {
            const float xv = xr[q];
            zi = fmaf(wiA[0][q], xv, zi);
            zf = fmaf(wiA[1][q], xv, zf);
            zg = fmaf(wiA[2][q], xv, zg);
            zo = fmaf(wiA[3][q], xv, zo);
        }
        const float ig = sigp(zi), fg = sigp(zf), gg = tanhp(zg), og = sigp(zo);
        c0 = ig * gg;
        const float h = og * tanhp(c0 * NS2);
#pragma unroll
        for (int q = 0; q < 6; q++)
            hb0[q] = __shfl_sync(0xffffffffu, h, q, 8);
    }

    // ---- main loop: iteration t does layer1(t) and layer0(t+1) ----
    for (int c = 0; c < NCHUNK; c++) {
        if (c + 1 < NCHUNK) stage(c + 1, (c + 1) & 1);
        __syncwarp();

        const float* bcur = sx[c & 1][warp] + e * CSTRIDE;
        const float* bnxt = sx[(c + 1) & 1][warp] + e * CSTRIDE;

#pragma unroll 4
        for (int dt = 0; dt < TCHUNK; dt++) {
            const float* xr = (dt < TCHUNK - 1) ? (bcur + (dt + 1) * 6) : bnxt;

            // two independent z chains: layer0 (t+1) and layer1 (t)
            float zi0 = bA[0], zf0 = bA[1], zg0 = bA[2], zo0 = bA[3];
            float zi1 = bB[0], zf1 = bB[1], zg1 = bB[2], zo1 = bB[3];
#pragma unroll
            for (int q = 0; q < 6; q++) {
                const float xv  = xr[q];
                const float h0v = hb0[q];
                const float h1v = hb1[q];
                zi0 = fmaf(wiA[0][q], xv, zi0);  zi0 = fmaf(whA[0][q], h0v, zi0);
                zf0 = fmaf(wiA[1][q], xv, zf0);  zf0 = fmaf(whA[1][q], h0v, zf0);
                zg0 = fmaf(wiA[2][q], xv, zg0);  zg0 = fmaf(whA[2][q], h0v, zg0);
                zo0 = fmaf(wiA[3][q], xv, zo0);  zo0 = fmaf(whA[3][q], h0v, zo0);
                zi1 = fmaf(wiB[0][q], h0v, zi1); zi1 = fmaf(whB[0][q], h1v, zi1);
                zf1 = fmaf(wiB[1][q], h0v, zf1); zf1 = fmaf(whB[1][q], h1v, zf1);
                zg1 = fmaf(wiB[2][q], h0v, zg1); zg1 = fmaf(whB[2][q], h1v, zg1);
                zo1 = fmaf(wiB[3][q], h0v, zo1); zo1 = fmaf(whB[3][q], h1v, zo1);
            }

            const float i0 = sigp(zi0), f0 = sigp(zf0), g0 = tanhp(zg0), o0 = sigp(zo0);
            const float i1 = sigp(zi1), f1 = sigp(zf1), g1 = tanhp(zg1), o1 = sigp(zo1);

            c0 = fmaf(f0, c0, i0 * g0);
            c1 = fmaf(f1, c1, i1 * g1);
            const float h0n = o0 * tanhp(c0 * NS2);
            const float h1n = o1 * tanhp(c1 * NS2);

            if (s < 6) so[warp][e * CSTRIDE + dt * 6 + s] = h1n;

#pragma unroll
            for (int q = 0; q < 6; q++) {
                hb0[q] = __shfl_sync(0xffffffffu, h0n, q, 8);
                hb1[q] = __shfl_sync(0xffffffffu, h1n, q, 8);
            }
        }
        __syncwarp();

        // ---- flush output chunk ----
        {
            const float4* src = reinterpret_cast<const float4*>(so[warp]);
#pragma unroll
            for (int i = 0; i < 6; i++) {
                int idx = i * 32 + lane;
                int ee  = idx / 48;
                int off = idx - ee * 48;
                float4* dst = reinterpret_cast<float4*>(
                    out + (size_t)(b0 + ee) * (T_LEN * 6) + c * (TCHUNK * 6));
                dst[off] = src[ee * CSTRIDE4 + off];
            }
        }
        __syncwarp();
    }
}

extern "C" void kernel_launch(void* const* d_in, const int* in_sizes, int n_in,
                              void* d_out, int out_size)
{
    const float* x    = (const float*)d_in[0];
    const float* wih0 = (const float*)d_in[1];
    const float* whh0 = (const float*)d_in[2];
    const float* bih0 = (const float*)d_in[3];
    const float* bhh0 = (const float*)d_in[4];
    const float* wih1 = (const float*)d_in[5];
    const float* whh1 = (const float*)d_in[6];
    const float* bih1 = (const float*)d_in[7];
    const float* bhh1 = (const float*)d_in[8];
    float* out = (float*)d_out;

    const int B = in_sizes[0] / (T_LEN * 6);                   // 4096
    const int grid = B / (WARPS_PER_BLOCK * ELEMS_PER_WARP);   // 256

    lstm2_kernel<<<grid, THREADS>>>(x, wih0, whh0, bih0, bhh0,
                                    wih1, whh1, bih1, bhh1, out);
}

// round 4
// speedup vs baseline: 1.6113x; 1.6113x over previous
#include <cuda_runtime.h>
#include <cstdint>

// 2-layer LSTM, H=6, F=6, B=4096, T=1024.
// 4 batch elements per warp; within each 8-lane segment, lane k (k<6) owns
// hidden index k and computes ALL FOUR gate rows (i,f,g,o) for that k.
// Software-pipelined: iteration t computes layer0(t+1) and layer1(t) as two
// independent dependency chains -> ~half the serial critical path per step.
// Weights pre-scaled by -log2(e) / -2log2(e) so activations are ex2+rcp only.

#define WARPS_PER_BLOCK 4
#define THREADS (WARPS_PER_BLOCK * 32)
#define ELEMS_PER_WARP 4
#define T_LEN 1024
#define TCHUNK 32
#define NCHUNK (T_LEN / TCHUNK)       // 32
#define CSTRIDE 200                   // padded per-element stride (floats)
#define CSTRIDE4 (CSTRIDE / 4)

#define L2E 1.4426950408889634f
#define NS2 (-2.0f * L2E)

__device__ __forceinline__ float ex2f(float x) {
    float y; asm("ex2.approx.f32 %0, %1;" : "=f"(y) : "f"(x)); return y;
}
__device__ __forceinline__ float rcpf(float x) {
    float y; asm("rcp.approx.f32 %0, %1;" : "=f"(y) : "f"(x)); return y;
}
__device__ __forceinline__ float sigp(float zs) {          // z pre-scaled by -log2(e)
    return rcpf(1.0f + ex2f(zs));
}
__device__ __forceinline__ float tanhp(float zs) {         // z pre-scaled by -2log2(e)
    return fmaf(2.0f, rcpf(1.0f + ex2f(zs)), -1.0f);
}

__global__ __launch_bounds__(THREADS, 1)
void lstm2_kernel(const float* __restrict__ x,
                  const float* __restrict__ wih0, const float* __restrict__ whh0,
                  const float* __restrict__ bih0, const float* __restrict__ bhh0,
                  const float* __restrict__ wih1, const float* __restrict__ whh1,
                  const float* __restrict__ bih1, const float* __restrict__ bhh1,
                  float* __restrict__ out)
{
    __shared__ float sx[2][WARPS_PER_BLOCK][ELEMS_PER_WARP * CSTRIDE];
    __shared__ float so[WARPS_PER_BLOCK][ELEMS_PER_WARP * CSTRIDE];

    const int lane = threadIdx.x & 31;
    const int warp = threadIdx.x >> 5;
    const int e    = lane >> 3;         // element within warp
    const int s    = lane & 7;          // sub-lane within segment
    const int k    = (s < 6) ? s : 0;   // hidden index owned

    const int b0 = (blockIdx.x * WARPS_PER_BLOCK + warp) * ELEMS_PER_WARP;

    // per-lane weight rows (i,f,g,o of hidden index k), pre-scaled
    float wiA[4][6], whA[4][6], wiB[4][6], whB[4][6], bA[4], bB[4];
#pragma unroll
    for (int g = 0; g < 4; g++) {
        const float sc = (g == 2) ? NS2 : (-L2E);
        const int row = g * 6 + k;
#pragma unroll
        for (int q = 0; q < 6; q++) {
            wiA[g][q] = wih0[row * 6 + q] * sc;
            whA[g][q] = whh0[row * 6 + q] * sc;
            wiB[g][q] = wih1[row * 6 + q] * sc;
            whB[g][q] = whh1[row * 6 + q] * sc;
        }
        bA[g] = (bih0[row] + bhh0[row]) * sc;
        bB[g] = (bih1[row] + bhh1[row]) * sc;
    }

    float hb0[6], hb1[6];
#pragma unroll
    for (int q = 0; q < 6; q++) { hb0[q] = 0.0f; hb1[q] = 0.0f; }
    float c0 = 0.0f, c1 = 0.0f;

    // ---- chunk staging helper (32 timesteps x 6 floats x 4 elements) ----
    auto stage = [&](int c, int buf) {
        float4* dst = reinterpret_cast<float4*>(sx[buf][warp]);
#pragma unroll
        for (int i = 0; i < 6; i++) {
            int idx = i * 32 + lane;                 // 0..191
            int ee  = idx / 48;
            int off = idx - ee * 48;
            const float4* src = reinterpret_cast<const float4*>(
                x + (size_t)(b0 + ee) * (T_LEN * 6) + c * (TCHUNK * 6));
            dst[ee * CSTRIDE4 + off] = src[off];
        }
    };

    // ---- prologue: stage chunk 0, compute layer0 for t=0 ----
    stage(0, 0);
    __syncwarp();
    {
        const float* xr = &sx[0][warp][e * CSTRIDE];
        float zi = bA[0], zf = bA[1], zg = bA[2], zo = bA[3];
#pragma unroll
        for (int q = 0; q < 6; q++) {
            const float xv = xr[q];
            zi = fmaf(wiA[0][q], xv, zi);
            zf = fmaf(wiA[1][q], xv, zf);
            zg = fmaf(wiA[2][q], xv, zg);
            zo = fmaf(wiA[3][q], xv, zo);
        }
        const float ig = sigp(zi), fg = sigp(zf), gg = tanhp(zg), og = sigp(zo);
        c0 = ig * gg;
        const float h = og * tanhp(c0 * NS2);
#pragma unroll
        for (int q = 0; q < 6; q++)
            hb0[q] = __shfl_sync(0xffffffffu, h, q, 8);
    }

    // ---- main loop: iteration t does layer1(t) and layer0(t+1) ----
    for (int c = 0; c < NCHUNK; c++) {
        if (c + 1 < NCHUNK) stage(c + 1, (c + 1) & 1);
        __syncwarp();

        const float* bcur = sx[c & 1][warp] + e * CSTRIDE;
        const float* bnxt = sx[(c + 1) & 1][warp] + e * CSTRIDE;

#pragma unroll 4
        for (int dt = 0; dt < TCHUNK; dt++) {
            const float* xr = (dt < TCHUNK - 1) ? (bcur + (dt + 1) * 6) : bnxt;

            // two independent z chains: layer0 (t+1) and layer1 (t)
            float zi0 = bA[0], zf0 = bA[1], zg0 = bA[2], zo0 = bA[3];
            float zi1 = bB[0], zf1 = bB[1], zg1 = bB[2], zo1 = bB[3];
#pragma unroll
            for (int q = 0; q < 6; q++) {
                const float xv  = xr[q];
                const float h0v = hb0[q];
                const float h1v = hb1[q];
                zi0 = fmaf(wiA[0][q], xv, zi0);  zi0 = fmaf(whA[0][q], h0v, zi0);
                zf0 = fmaf(wiA[1][q], xv, zf0);  zf0 = fmaf(whA[1][q], h0v, zf0);
                zg0 = fmaf(wiA[2][q], xv, zg0);  zg0 = fmaf(whA[2][q], h0v, zg0);
                zo0 = fmaf(wiA[3][q], xv, zo0);  zo0 = fmaf(whA[3][q], h0v, zo0);
                zi1 = fmaf(wiB[0][q], h0v, zi1); zi1 = fmaf(whB[0][q], h1v, zi1);
                zf1 = fmaf(wiB[1][q], h0v, zf1); zf1 = fmaf(whB[1][q], h1v, zf1);
                zg1 = fmaf(wiB[2][q], h0v, zg1); zg1 = fmaf(whB[2][q], h1v, zg1);
                zo1 = fmaf(wiB[3][q], h0v, zo1); zo1 = fmaf(whB[3][q], h1v, zo1);
            }

            const float i0 = sigp(zi0), f0 = sigp(zf0), g0 = tanhp(zg0), o0 = sigp(zo0);
            const float i1 = sigp(zi1), f1 = sigp(zf1), g1 = tanhp(zg1), o1 = sigp(zo1);

            c0 = fmaf(f0, c0, i0 * g0);
            c1 = fmaf(f1, c1, i1 * g1);
            const float h0n = o0 * tanhp(c0 * NS2);
            const float h1n = o1 * tanhp(c1 * NS2);

            if (s < 6) so[warp][e * CSTRIDE + dt * 6 + s] = h1n;

#pragma unroll
            for (int q = 0; q < 6; q++) {
                hb0[q] = __shfl_sync(0xffffffffu, h0n, q, 8);
                hb1[q] = __shfl_sync(0xffffffffu, h1n, q, 8);
            }
        }
        __syncwarp();

        // ---- flush output chunk ----
        {
            const float4* src = reinterpret_cast<const float4*>(so[warp]);
#pragma unroll
            for (int i = 0; i < 6; i++) {
                int idx = i * 32 + lane;
                int ee  = idx / 48;
                int off = idx - ee * 48;
                float4* dst = reinterpret_cast<float4*>(
                    out + (size_t)(b0 + ee) * (T_LEN * 6) + c * (TCHUNK * 6));
                dst[off] = src[ee * CSTRIDE4 + off];
            }
        }
        __syncwarp();
    }
}

extern "C" void kernel_launch(void* const* d_in, const int* in_sizes, int n_in,
                              void* d_out, int out_size)
{
    const float* x    = (const float*)d_in[0];
    const float* wih0 = (const float*)d_in[1];
    const float* whh0 = (const float*)d_in[2];
    const float* bih0 = (const float*)d_in[3];
    const float* bhh0 = (const float*)d_in[4];
    const float* wih1 = (const float*)d_in[5];
    const float* whh1 = (const float*)d_in[6];
    const float* bih1 = (const float*)d_in[7];
    const float* bhh1 = (const float*)d_in[8];
    float* out = (float*)d_out;

    const int B = in_sizes[0] / (T_LEN * 6);                   // 4096
    const int grid = B / (WARPS_PER_BLOCK * ELEMS_PER_WARP);   // 256

    lstm2_kernel<<<grid, THREADS>>>(x, wih0, whh0, bih0, bhh0,
                                    wih1, whh1, bih1, bhh1, out);
}

// round 5
// speedup vs baseline: 1.9706x; 1.2230x over previous
#include <cuda_runtime.h>
#include <cstdint>

// 2-layer LSTM, H=6, F=6, B=4096, T=1024.
// 4 batch elements per warp; lane k (k<6) of each 8-lane segment owns hidden
// index k and computes all four gate rows (i,f,g,o) for that k, for BOTH
// layers simultaneously via packed f32x2 FMAs:
//   lo half = layer0 gates (input x, recurrent h0)
//   hi half = layer1 gates (input h0, recurrent h1)
// Activations via MUFU.TANH (tanh.approx.f32); sigmoid = 0.5*tanh(z/2)+0.5
// with the 0.5 pre-scale folded into the weights.

#define WARPS_PER_BLOCK 4
#define THREADS (WARPS_PER_BLOCK * 32)
#define ELEMS_PER_WARP 4
#define T_LEN 1024
#define TCHUNK 32
#define NCHUNK (T_LEN / TCHUNK)
#define CSTRIDE 200                 // padded per-element smem stride (floats)
#define CSTRIDE4 (CSTRIDE / 4)

__device__ __forceinline__ float tanha(float x) {
    float y; asm("tanh.approx.f32 %0, %1;" : "=f"(y) : "f"(x)); return y;
}
__device__ __forceinline__ unsigned long long pk2(float lo, float hi) {
    unsigned long long r;
    asm("mov.b64 %0, {%1, %2};" : "=l"(r) : "f"(lo), "f"(hi));
    return r;
}
__device__ __forceinline__ void upk2(float& lo, float& hi, unsigned long long v) {
    asm("mov.b64 {%0, %1}, %2;" : "=f"(lo), "=f"(hi) : "l"(v));
}
__device__ __forceinline__ unsigned long long fma2(unsigned long long a,
                                                   unsigned long long b,
                                                   unsigned long long c) {
    unsigned long long d;
    asm("fma.rn.f32x2 %0, %1, %2, %3;" : "=l"(d) : "l"(a), "l"(b), "l"(c));
    return d;
}

__global__ __launch_bounds__(THREADS, 1)
void lstm2_kernel(const float* __restrict__ x,
                  const float* __restrict__ wih0, const float* __restrict__ whh0,
                  const float* __restrict__ bih0, const float* __restrict__ bhh0,
                  const float* __restrict__ wih1, const float* __restrict__ whh1,
                  const float* __restrict__ bih1, const float* __restrict__ bhh1,
                  float* __restrict__ out)
{
    __shared__ float sx[2][WARPS_PER_BLOCK][ELEMS_PER_WARP * CSTRIDE];
    __shared__ float so[WARPS_PER_BLOCK][ELEMS_PER_WARP * CSTRIDE];

    const int lane = threadIdx.x & 31;
    const int warp = threadIdx.x >> 5;
    const int e    = lane >> 3;
    const int s    = lane & 7;
    const int k    = (s < 6) ? s : 0;

    const int b0 = (blockIdx.x * WARPS_PER_BLOCK + warp) * ELEMS_PER_WARP;

    // Packed weights: lo = layer0 row, hi = layer1 row. Sigmoid rows (i,f,o)
    // pre-scaled by 0.5 (for sigmoid-via-tanh); g rows unscaled.
    unsigned long long wxp[4][6], whp[4][6], bp[4];
#pragma unroll
    for (int g = 0; g < 4; g++) {
        const float sc = (g == 2) ? 1.0f : 0.5f;
        const int row = g * 6 + k;
#pragma unroll
        for (int q = 0; q < 6; q++) {
            wxp[g][q] = pk2(wih0[row * 6 + q] * sc, wih1[row * 6 + q] * sc);
            whp[g][q] = pk2(whh0[row * 6 + q] * sc, whh1[row * 6 + q] * sc);
        }
        bp[g] = pk2((bih0[row] + bhh0[row]) * sc, (bih1[row] + bhh1[row]) * sc);
    }

    float hb0[6], hb1[6];
#pragma unroll
    for (int q = 0; q < 6; q++) { hb0[q] = 0.0f; hb1[q] = 0.0f; }
    float c0 = 0.0f, c1 = 0.0f;

    auto stage = [&](int c, int buf) {
        float4* dst = reinterpret_cast<float4*>(sx[buf][warp]);
#pragma unroll
        for (int i = 0; i < 6; i++) {
            int idx = i * 32 + lane;
            int ee  = idx / 48;
            int off = idx - ee * 48;
            const float4* src = reinterpret_cast<const float4*>(
                x + (size_t)(b0 + ee) * (T_LEN * 6) + c * (TCHUNK * 6));
            dst[ee * CSTRIDE4 + off] = src[off];
        }
    };

    // ---- prologue: stage chunk 0; layer0 at t=0 (h0=0) ----
    stage(0, 0);
    __syncwarp();
    {
        const float* xr = &sx[0][warp][e * CSTRIDE];
        unsigned long long z[4];
#pragma unroll
        for (int g = 0; g < 4; g++) z[g] = bp[g];
#pragma unroll
        for (int q = 0; q < 6; q++) {
            const unsigned long long inp = pk2(xr[q], 0.0f);
#pragma unroll
            for (int g = 0; g < 4; g++) z[g] = fma2(wxp[g][q], inp, z[g]);
        }
        float zi, zf, zg, zo, dum;
        upk2(zi, dum, z[0]); upk2(zf, dum, z[1]);
        upk2(zg, dum, z[2]); upk2(zo, dum, z[3]);
        const float i0 = fmaf(0.5f, tanha(zi), 0.5f);
        const float g0 = tanha(zg);
        const float o0 = fmaf(0.5f, tanha(zo), 0.5f);
        (void)zf;                      // f*c with c=0
        c0 = i0 * g0;
        const float h = o0 * tanha(c0);
#pragma unroll
        for (int q = 0; q < 6; q++)
            hb0[q] = __shfl_sync(0xffffffffu, h, q, 8);
    }

    // ---- main loop: iteration t computes layer0(t+1) and layer1(t) ----
    for (int c = 0; c < NCHUNK; c++) {
        if (c + 1 < NCHUNK) stage(c + 1, (c + 1) & 1);
        __syncwarp();

        const float* bcur = sx[c & 1][warp] + e * CSTRIDE;
        const float* bnxt = sx[(c + 1) & 1][warp] + e * CSTRIDE;

#pragma unroll 4
        for (int dt = 0; dt < TCHUNK; dt++) {
            const float* xr = (dt < TCHUNK - 1) ? (bcur + (dt + 1) * 6) : bnxt;

            unsigned long long z[4];
#pragma unroll
            for (int g = 0; g < 4; g++) z[g] = bp[g];
#pragma unroll
            for (int q = 0; q < 6; q++) {
                // lo: layer0 input x(t+1); hi: layer1 input h0(t)
                const unsigned long long inp = pk2(xr[q], hb0[q]);
                // lo: layer0 recurrent h0(t); hi: layer1 recurrent h1(t-1)
                const unsigned long long rec = pk2(hb0[q], hb1[q]);
#pragma unroll
                for (int g = 0; g < 4; g++) {
                    z[g] = fma2(wxp[g][q], inp, z[g]);
                    z[g] = fma2(whp[g][q], rec, z[g]);
                }
            }

            float zi0, zi1, zf0, zf1, zg0, zg1, zo0, zo1;
            upk2(zi0, zi1, z[0]); upk2(zf0, zf1, z[1]);
            upk2(zg0, zg1, z[2]); upk2(zo0, zo1, z[3]);

            const float i0 = fmaf(0.5f, tanha(zi0), 0.5f);
            const float f0 = fmaf(0.5f, tanha(zf0), 0.5f);
            const float g0 = tanha(zg0);
            const float o0 = fmaf(0.5f, tanha(zo0), 0.5f);
            const float i1 = fmaf(0.5f, tanha(zi1), 0.5f);
            const float f1 = fmaf(0.5f, tanha(zf1), 0.5f);
            const float g1 = tanha(zg1);
            const float o1 = fmaf(0.5f, tanha(zo1), 0.5f);

            c0 = fmaf(f0, c0, i0 * g0);
            c1 = fmaf(f1, c1, i1 * g1);
            const float h0n = o0 * tanha(c0);
            const float h1n = o1 * tanha(c1);

            if (s < 6) so[warp][e * CSTRIDE + dt * 6 + s] = h1n;

#pragma unroll
            for (int q = 0; q < 6; q++) {
                hb0[q] = __shfl_sync(0xffffffffu, h0n, q, 8);
                hb1[q] = __shfl_sync(0xffffffffu, h1n, q, 8);
            }
        }
        __syncwarp();

        {
            const float4* src = reinterpret_cast<const float4*>(so[warp]);
#pragma unroll
            for (int i = 0; i < 6; i++) {
                int idx = i * 32 + lane;
                int ee  = idx / 48;
                int off = idx - ee * 48;
                float4* dst = reinterpret_cast<float4*>(
                    out + (size_t)(b0 + ee) * (T_LEN * 6) + c * (TCHUNK * 6));
                dst[off] = src[ee * CSTRIDE4 + off];
            }
        }
        __syncwarp();
    }
}

extern "C" void kernel_launch(void* const* d_in, const int* in_sizes, int n_in,
                              void* d_out, int out_size)
{
    const float* x    = (const float*)d_in[0];
    const float* wih0 = (const float*)d_in[1];
    const float* whh0 = (const float*)d_in[2];
    const float* bih0 = (const float*)d_in[3];
    const float* bhh0 = (const float*)d_in[4];
    const float* wih1 = (const float*)d_in[5];
    const float* whh1 = (const float*)d_in[6];
    const float* bih1 = (const float*)d_in[7];
    const float* bhh1 = (const float*)d_in[8];
    float* out = (float*)d_out;

    const int B = in_sizes[0] / (T_LEN * 6);
    const int grid = B / (WARPS_PER_BLOCK * ELEMS_PER_WARP);

    lstm2_kernel<<<grid, THREADS>>>(x, wih0, whh0, bih0, bhh0,
                                    wih1, whh1, bih1, bhh1, out);
}